// round 13
// baseline (speedup 1.0000x reference)
#include <cuda_runtime.h>
#include <stdint.h>

#define GH 52
#define GW 52
#define NB 5
#define NBOX 13520                 // 52*52*5
#define ROWBITS 288                // padded positions per grid row (260 used)
#define PWORDS 468
#define PPOS   (PWORDS*32)         // 14976 padded positions
#define IOU_T  0.4f
#define STK    80
#define M48    0x0000FFFFFFFFFFFFull
#define ROWF   (GW*25)             // floats per input grid row = 1300
#define DEC_T  864                 // 3 * 288

// Per-position record (padded layout), one 64-bit word:
//   bits [0:16)  pred mask row dy=-1 (15 bits, bit (dx+1)*5+bb)
//   bits[16:32)  pred mask row dy= 0
//   bits[32:48)  pred mask row dy=+1
//   bits[48:64)  memo state: 0=unknown, 1=kept, 2=suppressed
// Padding positions are never written and stay zero.
__device__ ushort4 g_pm[PPOS];

// ---------------------------------------------------------------------------
// Kernel 1: decode + predecessor masks, smem-staged.
// One block per grid row; rows gy-1..gy+1 staged into smem with coalesced
// loads; each thread = (dyI, gx, b) computes 15 IoUs from smem.
// Identical fp32 op sequence as before (values pass through smem unchanged).
// ---------------------------------------------------------------------------
__global__ void __launch_bounds__(DEC_T)
decode_kernel(const float* __restrict__ x, float* __restrict__ out)
{
    __shared__ float sx_[3 * ROWF];          // 15.6 KB
    int gy = blockIdx.x;
    int t  = threadIdx.x;

    for (int i = t; i < 3 * ROWF; i += DEC_T) {
        int r  = i / ROWF;                   // 0,1,2 -> row gy-1+r
        int c  = i - r * ROWF;
        int ny = gy + r - 1;
        sx_[i] = ((unsigned)ny < GH) ? x[ny * ROWF + c] : 0.0f;
    }
    __syncthreads();

    int dyI = t / 288;                       // 0,1,2
    int qq  = t - dyI * 288;
    if (qq >= 260) return;
    int gx = qq / 5;
    int b  = qq - gx * 5;
    int j  = (gy * GW + gx) * NB + b;

    const float sx = 416.0f / GW;            // 8
    const float sy = 416.0f / GH;            // 8

    const float* p = &sx_[ROWF + gx * 25 + b * 5];
    float c0 = p[0], c1 = p[1], c2 = p[2], c3 = p[3], sj = p[4];

    float cx = (c0 + (float)gx) * sx;
    float w  = c2 * sx;
    float cy = (c1 + (float)gy) * sy;
    float h  = c3 * sy;
    cy = 416.0f - cy;
    float jx1 = cx - w * 0.5f, jy1 = cy - h * 0.5f;
    float jx2 = cx + w * 0.5f, jy2 = cy + h * 0.5f;

    int pos = gy * ROWBITS + gx * 5 + b;

    if (dyI == 1) {
        float* o = out + j * 5;
        o[0] = jx1; o[1] = jy1; o[2] = jx2; o[3] = jy2;
        ((unsigned short*)&g_pm[pos])[3] = 0;   // memo reset (replay-safe)
        // o[4] written by resolve_kernel.
    }

    float aj = fmaxf(jx2 - jx1, 0.0f) * fmaxf(jy2 - jy1, 0.0f);

    unsigned mask = 0;
    int ny = gy + dyI - 1;
    if ((unsigned)ny < GH) {
        const float* rowp = &sx_[dyI * ROWF];
        #pragma unroll
        for (int dxi = 0; dxi < 3; dxi++) {
            int nx = gx + dxi - 1;
            if ((unsigned)nx >= GW) continue;
            int ncell = ny * GW + nx;
            const float* cp = rowp + nx * 25;

            #pragma unroll
            for (int bb = 0; bb < NB; bb++) {
                int i = ncell * NB + bb;
                float si = cp[bb * 5 + 4];
                bool higher = (si > sj) || (si == sj && i < j);
                float d0 = cp[bb * 5 + 0], d1 = cp[bb * 5 + 1];
                float d2 = cp[bb * 5 + 2], d3 = cp[bb * 5 + 3];
                float icx = (d0 + (float)nx) * sx;
                float iw_ = d2 * sx;
                float icy = (d1 + (float)ny) * sy;
                float ih_ = d3 * sy;
                icy = 416.0f - icy;
                float ix1 = icx - iw_ * 0.5f, iy1 = icy - ih_ * 0.5f;
                float ix2 = icx + iw_ * 0.5f, iy2 = icy + ih_ * 0.5f;

                float iw = fmaxf(fminf(ix2, jx2) - fmaxf(ix1, jx1), 0.0f);
                float ih = fmaxf(fminf(iy2, jy2) - fmaxf(iy1, jy1), 0.0f);
                float inter = iw * ih;
                float ai  = fmaxf(ix2 - ix1, 0.0f) * fmaxf(iy2 - iy1, 0.0f);
                float uni = ai + aj - inter;
                float iou = (uni > 0.0f) ? inter / fmaxf(uni, 1e-12f) : 0.0f;
                bool on = (iou > IOU_T) && higher && (i != j);
                mask |= (on ? 1u : 0u) << (dxi * 5 + bb);
            }
        }
    }
    ((unsigned short*)&g_pm[pos])[dyI] = (unsigned short)mask;
}

// ---------------------------------------------------------------------------
// Kernel 2: per-box memoized DFS, one thread per box, no barriers.
// Per scan step: extract up to TWO sibling preds and issue both 64-bit
// mask+state loads back-to-back (MLP) before consuming the first.
// Stale L1 reads are safe: state is monotone 0 -> {1,2} with deterministic
// final value; a stale 0 only causes recomputation. Well-founded recursion
// => termination; unique fixpoint == exact greedy NMS.
// Addressing: bit k -> pred = pbase + (k>>4)*ROWBITS + (k&15),
// pbase = pos - bb - ROWBITS - 5.
// ---------------------------------------------------------------------------
__device__ __forceinline__ void set_state(int pos, unsigned short v)
{
    ((unsigned short*)&g_pm[pos])[3] = v;
}

__device__ __forceinline__ int bb_of(int q)
{
    int bb = q - (q >= 5 ? 5 : 0);
    return bb - (bb >= 5 ? 5 : 0);
}

__global__ void __launch_bounds__(256)
resolve_kernel(const float* __restrict__ x, float* __restrict__ out)
{
    int j = blockIdx.x * blockDim.x + threadIdx.x;
    if (j >= NBOX) return;
    int row = j / 260;
    int rem = j - row * 260;
    int pos = row * ROWBITS + rem;

    const uint64_t* gm = (const uint64_t*)g_pm;

    uint64_t w0 = gm[pos];
    int res = (int)(w0 >> 48);
    if (res == 0) {
        if ((w0 & M48) == 0ull) {
            res = 1;
            set_state(pos, 1);
        } else {
            int      fpos[STK], fpb[STK];
            uint64_t frem[STK];
            fpos[0] = pos;
            fpb[0]  = pos - (rem % 5) - ROWBITS - 5;
            frem[0] = w0 & M48;
            int sp = 1;
            while (sp > 0) {
                uint64_t r = frem[sp - 1];
                int fin = 0;
                if (r == 0ull) {
                    fin = 1;                           // no kept pred -> kept
                } else {
                    int pb = fpb[sp - 1];
                    // extract up to 2 sibling preds, issue both loads (MLP)
                    int k0 = __ffsll((long long)r) - 1;
                    uint64_t r1 = r & (r - 1);
                    int q0    = k0 & 15;
                    int pred0 = pb + (k0 >> 4) * ROWBITS + q0;
                    uint64_t wp0 = gm[pred0];
                    int pred1 = -1;
                    uint64_t wp1 = 0, r2 = r1;
                    if (r1) {
                        int k1 = __ffsll((long long)r1) - 1;
                        r2 = r1 & (r1 - 1);
                        int q1 = k1 & 15;
                        pred1 = pb + (k1 >> 4) * ROWBITS + q1;
                        wp1 = gm[pred1];
                    }

                    // ---- consume pred0 ----
                    frem[sp - 1] = r1;
                    int sv0 = (int)(wp0 >> 48);
                    if (sv0 == 1) {
                        fin = 2;
                    } else if (sv0 == 0) {
                        uint64_t m0 = wp0 & M48;
                        if (m0 == 0ull) {
                            set_state(pred0, 1);
                            fin = 2;
                        } else if (sp < STK) {
                            fpos[sp] = pred0;
                            fpb[sp]  = pred0 - bb_of(q0) - ROWBITS - 5;
                            frem[sp] = m0;
                            sp++;
                            continue;                  // descend (wp1 unused)
                        } else {
                            volatile unsigned short* vs =
                                &((unsigned short*)&g_pm[pred0])[3];
                            unsigned short v;
                            do { v = *vs; } while (v == 0);
                            if (v == 1) fin = 2;
                        }
                    }
                    // sv0 == 2 (or resolved above): consume pred1 if loaded
                    if (!fin && pred1 >= 0) {
                        frem[sp - 1] = r2;
                        int sv1 = (int)(wp1 >> 48);
                        if (sv1 == 1) {
                            fin = 2;
                        } else if (sv1 == 0) {
                            uint64_t m1 = wp1 & M48;
                            if (m1 == 0ull) {
                                set_state(pred1, 1);
                                fin = 2;
                            } else if (sp < STK) {
                                int q1b = pred1 % ROWBITS;
                                fpos[sp] = pred1;
                                fpb[sp]  = pred1 - (q1b % 5) - ROWBITS - 5;
                                frem[sp] = m1;
                                sp++;
                                continue;              // descend
                            } else {
                                volatile unsigned short* vs =
                                    &((unsigned short*)&g_pm[pred1])[3];
                                unsigned short v;
                                do { v = *vs; } while (v == 0);
                                if (v == 1) fin = 2;
                            }
                        }
                        // sv1 == 2: both suppressed, loop continues
                    }
                    if (!fin && frem[sp - 1] == 0ull) fin = 1;
                    if (!fin) continue;                // more siblings to scan
                }
                // ---- pop / propagate ----
                set_state(fpos[sp - 1], (unsigned short)fin);
                sp--;
                if (sp == 0) {
                    res = fin;
                } else if (fin == 1) {                 // kept child -> parent supp
                    set_state(fpos[sp - 1], 2);
                    sp--;
                    if (sp == 0) res = 2;
                }
            }
        }
    }

    out[j * 5 + 4] = (res == 1) ? __ldg(&x[j * 5 + 4]) : 0.0f;
}

// ---------------------------------------------------------------------------
extern "C" void kernel_launch(void* const* d_in, const int* in_sizes, int n_in,
                              void* d_out, int out_size)
{
    const float* x   = (const float*)d_in[0];
    float*       out = (float*)d_out;

    decode_kernel<<<GH, DEC_T>>>(x, out);
    resolve_kernel<<<(NBOX + 255) / 256, 256>>>(x, out);
}

// round 14
// speedup vs baseline: 1.1348x; 1.1348x over previous
#include <cuda_runtime.h>
#include <stdint.h>

#define GH 52
#define GW 52
#define NB 5
#define NBOX 13520                 // 52*52*5
#define ROWBITS 288                // padded positions per grid row (260 used)
#define PWORDS 468
#define PPOS   (PWORDS*32)         // 14976 padded positions
#define IOU_T  0.4f
#define STK    80
#define M48    0x0000FFFFFFFFFFFFull

// Per-position record (padded layout), one 64-bit word:
//   bits [0:16)  pred mask row dy=-1 (15 bits, bit (dx+1)*5+bb)
//   bits[16:32)  pred mask row dy= 0
//   bits[32:48)  pred mask row dy=+1
//   bits[48:64)  memo state: 0=unknown, 1=kept, 2=suppressed
// Padding positions are never written and stay zero.
__device__ ushort4 g_pm[PPOS];

// ---------------------------------------------------------------------------
// Kernel 1: decode + predecessor masks (R12 version — proven fastest).
// One thread per (box, dyRow); branchless q[25] cell preload (L1-hit heavy,
// fully parallel). Identical fp32 op sequence as the reference decode.
// ---------------------------------------------------------------------------
__global__ void decode_kernel(const float* __restrict__ x, float* __restrict__ out)
{
    int id = blockIdx.x * blockDim.x + threadIdx.x;
    if (id >= 3 * NBOX) return;
    int dyI = id / NBOX;            // 0,1,2 -> dy = dyI-1
    int j   = id - dyI * NBOX;

    int cell = j / NB;
    int b    = j - cell * NB;
    int gy   = cell / GW;
    int gx   = cell - gy * GW;

    const float sx = 416.0f / GW;   // 8
    const float sy = 416.0f / GH;   // 8

    const float* p = x + j * 5;
    float c0 = p[0], c1 = p[1], c2 = p[2], c3 = p[3], sj = p[4];

    float cx = (c0 + (float)gx) * sx;
    float w  = c2 * sx;
    float cy = (c1 + (float)gy) * sy;
    float h  = c3 * sy;
    cy = 416.0f - cy;
    float jx1 = cx - w * 0.5f, jy1 = cy - h * 0.5f;
    float jx2 = cx + w * 0.5f, jy2 = cy + h * 0.5f;

    int pos = gy * ROWBITS + gx * 5 + b;

    if (dyI == 1) {
        float* o = out + j * 5;
        o[0] = jx1; o[1] = jy1; o[2] = jx2; o[3] = jy2;
        ((unsigned short*)&g_pm[pos])[3] = 0;   // memo reset (replay-safe)
        // o[4] written by resolve_kernel.
    }

    float aj = fmaxf(jx2 - jx1, 0.0f) * fmaxf(jy2 - jy1, 0.0f);

    unsigned mask = 0;
    int ny = gy + dyI - 1;
    if ((unsigned)ny < GH) {
        #pragma unroll
        for (int dxi = 0; dxi < 3; dxi++) {
            int nx = gx + dxi - 1;
            if ((unsigned)nx >= GW) continue;
            int ncell = ny * GW + nx;
            const float* cp = x + ncell * 25;
            float q[25];
            #pragma unroll
            for (int k = 0; k < 25; k++) q[k] = cp[k];

            #pragma unroll
            for (int bb = 0; bb < NB; bb++) {
                int i = ncell * NB + bb;
                float si = q[bb * 5 + 4];
                bool higher = (si > sj) || (si == sj && i < j);
                float d0 = q[bb * 5 + 0], d1 = q[bb * 5 + 1];
                float d2 = q[bb * 5 + 2], d3 = q[bb * 5 + 3];
                float icx = (d0 + (float)nx) * sx;
                float iw_ = d2 * sx;
                float icy = (d1 + (float)ny) * sy;
                float ih_ = d3 * sy;
                icy = 416.0f - icy;
                float ix1 = icx - iw_ * 0.5f, iy1 = icy - ih_ * 0.5f;
                float ix2 = icx + iw_ * 0.5f, iy2 = icy + ih_ * 0.5f;

                float iw = fmaxf(fminf(ix2, jx2) - fmaxf(ix1, jx1), 0.0f);
                float ih = fmaxf(fminf(iy2, jy2) - fmaxf(iy1, jy1), 0.0f);
                float inter = iw * ih;
                float ai  = fmaxf(ix2 - ix1, 0.0f) * fmaxf(iy2 - iy1, 0.0f);
                float uni = ai + aj - inter;
                float iou = (uni > 0.0f) ? inter / fmaxf(uni, 1e-12f) : 0.0f;
                bool on = (iou > IOU_T) && higher && (i != j);
                mask |= (on ? 1u : 0u) << (dxi * 5 + bb);
            }
        }
    }
    ((unsigned short*)&g_pm[pos])[dyI] = (unsigned short)mask;
}

// ---------------------------------------------------------------------------
// Kernel 2: per-box memoized DFS with 2-wide sibling prefetch (R13 version —
// proven fastest). One thread per box, no barriers.
// Stale L1 reads are safe: state is monotone 0 -> {1,2} with deterministic
// final value; a stale 0 only causes recomputation. Well-founded recursion
// => termination; unique fixpoint == exact greedy NMS.
// Addressing: bit k -> pred = pbase + (k>>4)*ROWBITS + (k&15),
// pbase = pos - bb - ROWBITS - 5.
// ---------------------------------------------------------------------------
__device__ __forceinline__ void set_state(int pos, unsigned short v)
{
    ((unsigned short*)&g_pm[pos])[3] = v;
}

__device__ __forceinline__ int bb_of(int q)
{
    int bb = q - (q >= 5 ? 5 : 0);
    return bb - (bb >= 5 ? 5 : 0);
}

__global__ void __launch_bounds__(256)
resolve_kernel(const float* __restrict__ x, float* __restrict__ out)
{
    int j = blockIdx.x * blockDim.x + threadIdx.x;
    if (j >= NBOX) return;
    int row = j / 260;
    int rem = j - row * 260;
    int pos = row * ROWBITS + rem;

    const uint64_t* gm = (const uint64_t*)g_pm;

    uint64_t w0 = gm[pos];
    int res = (int)(w0 >> 48);
    if (res == 0) {
        if ((w0 & M48) == 0ull) {
            res = 1;
            set_state(pos, 1);
        } else {
            int      fpos[STK], fpb[STK];
            uint64_t frem[STK];
            fpos[0] = pos;
            fpb[0]  = pos - (rem % 5) - ROWBITS - 5;
            frem[0] = w0 & M48;
            int sp = 1;
            while (sp > 0) {
                uint64_t r = frem[sp - 1];
                int fin = 0;
                if (r == 0ull) {
                    fin = 1;                           // no kept pred -> kept
                } else {
                    int pb = fpb[sp - 1];
                    // extract up to 2 sibling preds, issue both loads (MLP)
                    int k0 = __ffsll((long long)r) - 1;
                    uint64_t r1 = r & (r - 1);
                    int q0    = k0 & 15;
                    int pred0 = pb + (k0 >> 4) * ROWBITS + q0;
                    uint64_t wp0 = gm[pred0];
                    int pred1 = -1;
                    uint64_t wp1 = 0, r2 = r1;
                    if (r1) {
                        int k1 = __ffsll((long long)r1) - 1;
                        r2 = r1 & (r1 - 1);
                        int q1 = k1 & 15;
                        pred1 = pb + (k1 >> 4) * ROWBITS + q1;
                        wp1 = gm[pred1];
                    }

                    // ---- consume pred0 ----
                    frem[sp - 1] = r1;
                    int sv0 = (int)(wp0 >> 48);
                    if (sv0 == 1) {
                        fin = 2;
                    } else if (sv0 == 0) {
                        uint64_t m0 = wp0 & M48;
                        if (m0 == 0ull) {
                            set_state(pred0, 1);
                            fin = 2;
                        } else if (sp < STK) {
                            fpos[sp] = pred0;
                            fpb[sp]  = pred0 - bb_of(q0) - ROWBITS - 5;
                            frem[sp] = m0;
                            sp++;
                            continue;                  // descend (wp1 unused)
                        } else {
                            volatile unsigned short* vs =
                                &((unsigned short*)&g_pm[pred0])[3];
                            unsigned short v;
                            do { v = *vs; } while (v == 0);
                            if (v == 1) fin = 2;
                        }
                    }
                    // sv0 == 2 (or resolved above): consume pred1 if loaded
                    if (!fin && pred1 >= 0) {
                        frem[sp - 1] = r2;
                        int sv1 = (int)(wp1 >> 48);
                        if (sv1 == 1) {
                            fin = 2;
                        } else if (sv1 == 0) {
                            uint64_t m1 = wp1 & M48;
                            if (m1 == 0ull) {
                                set_state(pred1, 1);
                                fin = 2;
                            } else if (sp < STK) {
                                int q1b = pred1 % ROWBITS;
                                fpos[sp] = pred1;
                                fpb[sp]  = pred1 - (q1b % 5) - ROWBITS - 5;
                                frem[sp] = m1;
                                sp++;
                                continue;              // descend
                            } else {
                                volatile unsigned short* vs =
                                    &((unsigned short*)&g_pm[pred1])[3];
                                unsigned short v;
                                do { v = *vs; } while (v == 0);
                                if (v == 1) fin = 2;
                            }
                        }
                        // sv1 == 2: both suppressed, loop continues
                    }
                    if (!fin && frem[sp - 1] == 0ull) fin = 1;
                    if (!fin) continue;                // more siblings to scan
                }
                // ---- pop / propagate ----
                set_state(fpos[sp - 1], (unsigned short)fin);
                sp--;
                if (sp == 0) {
                    res = fin;
                } else if (fin == 1) {                 // kept child -> parent supp
                    set_state(fpos[sp - 1], 2);
                    sp--;
                    if (sp == 0) res = 2;
                }
            }
        }
    }

    out[j * 5 + 4] = (res == 1) ? __ldg(&x[j * 5 + 4]) : 0.0f;
}

// ---------------------------------------------------------------------------
extern "C" void kernel_launch(void* const* d_in, const int* in_sizes, int n_in,
                              void* d_out, int out_size)
{
    const float* x   = (const float*)d_in[0];
    float*       out = (float*)d_out;

    decode_kernel<<<(3 * NBOX + 255) / 256, 256>>>(x, out);
    resolve_kernel<<<(NBOX + 255) / 256, 256>>>(x, out);
}